// round 16
// baseline (speedup 1.0000x reference)
#include <cuda_runtime.h>
#include <cuda_fp16.h>
#include <mma.h>

using namespace nvcuda;

#define N_NODES 50000
#define FEAT 128
#define E_MAX 1600000

// ---------------- scratch (static device globals; no allocation) ----------------
__device__ __align__(16) float  g_buf0[(size_t)N_NODES * FEAT];   // fp32 aggregation output
__device__ __align__(16) __half g_h16[(size_t)N_NODES * FEAT];    // fp16 GEMM output (gather payload)
__device__ float g_rs_out[N_NODES];
__device__ float g_rs_in[N_NODES];
__device__ int   g_deg_out[N_NODES];
__device__ int   g_deg_in[N_NODES];
__device__ int   g_offsets[N_NODES];
__device__ int   g_cursor[N_NODES];
__device__ int   g_csr_src[E_MAX];
__device__ int   g_seg_counter[1];

// ---------------- degree count (4 edges/thread via int4) ----------------
__global__ void count_deg_kernel(const int* __restrict__ src, const int* __restrict__ dst,
                                 int* deg_out, int* deg_in, int e) {
    int i = blockIdx.x * blockDim.x + threadIdx.x;
    int e4 = e >> 2;
    if (i < e4) {
        int4 s = __ldg((const int4*)src + i);
        int4 d = __ldg((const int4*)dst + i);
        atomicAdd(&deg_out[s.x], 1); atomicAdd(&deg_out[s.y], 1);
        atomicAdd(&deg_out[s.z], 1); atomicAdd(&deg_out[s.w], 1);
        atomicAdd(&deg_in[d.x], 1);  atomicAdd(&deg_in[d.y], 1);
        atomicAdd(&deg_in[d.z], 1);  atomicAdd(&deg_in[d.w], 1);
    }
    if (blockIdx.x == 0 && threadIdx.x < (e & 3)) {
        int t = e4 * 4 + threadIdx.x;
        atomicAdd(&deg_out[src[t]], 1);
        atomicAdd(&deg_in[dst[t]], 1);
    }
}

// ---------------- single-kernel segment assignment + rs finalize ----------------
// Order-free CSR segments: warp-local exclusive scan of deg_in, lane31 claims a
// global base with one atomicAdd. Segments tile [0, e) disjointly; gather uses
// beg = offsets[i], end = beg + deg_in[i] (node order irrelevant).
__global__ void segment_assign_kernel(const int* __restrict__ deg_in, const int* __restrict__ deg_out,
                                      int* __restrict__ offsets, int* __restrict__ cursor,
                                      float* __restrict__ rs_out, float* __restrict__ rs_in,
                                      int* __restrict__ counter, int n) {
    int i = blockIdx.x * blockDim.x + threadIdx.x;
    int lane = threadIdx.x & 31;
    int v = (i < n) ? deg_in[i] : 0;
    if (i < n) {
        rs_in[i]  = rsqrtf((float)max(v, 1));
        rs_out[i] = rsqrtf((float)max(deg_out[i], 1));
    }
    int x = v;
    #pragma unroll
    for (int o = 1; o < 32; o <<= 1) {
        int y = __shfl_up_sync(0xffffffffu, x, o);
        if (lane >= o) x += y;
    }
    int excl = x - v;
    int warpsum = __shfl_sync(0xffffffffu, x, 31);
    int base = 0;
    if (lane == 31) base = atomicAdd(counter, warpsum);
    base = __shfl_sync(0xffffffffu, base, 31);
    if (i < n) {
        int o = base + excl;
        offsets[i] = o;
        cursor[i] = o;
    }
}

// ---------------- csr fill (4 edges/thread via int4) ----------------
__global__ void csr_fill_kernel(const int* __restrict__ src, const int* __restrict__ dst,
                                int* cursor, int* __restrict__ csr_src, int e) {
    int i = blockIdx.x * blockDim.x + threadIdx.x;
    int e4 = e >> 2;
    if (i < e4) {
        int4 s = __ldg((const int4*)src + i);
        int4 d = __ldg((const int4*)dst + i);
        int p0 = atomicAdd(&cursor[d.x], 1);
        int p1 = atomicAdd(&cursor[d.y], 1);
        int p2 = atomicAdd(&cursor[d.z], 1);
        int p3 = atomicAdd(&cursor[d.w], 1);
        csr_src[p0] = s.x; csr_src[p1] = s.y;
        csr_src[p2] = s.z; csr_src[p3] = s.w;
    }
    if (blockIdx.x == 0 && threadIdx.x < (e & 3)) {
        int t = e4 * 4 + threadIdx.x;
        int pos = atomicAdd(&cursor[dst[t]], 1);
        csr_src[pos] = src[t];
    }
}

// ---------------- fused tensor-core GEMM (wmma fp16 in, fp32 acc) ----------------
// Y[r,:] = pre(X[r,:]) @ W  (+ post_bias)
// PRE==1: x * rs_a[r]
// PRE==2: relu(x * rs_a[r] + pre_bias[c]) * rs_b[r]
// PRE==3: x * rs_a[r] + pre_bias[c]
template <int N_OUT, int PRE, int HALF_OUT>
__global__ void gemm_tc_kernel(const float* __restrict__ X, const float* __restrict__ W,
                               void* __restrict__ Yv, int n_rows,
                               const float* __restrict__ rs_a,
                               const float* __restrict__ rs_b,
                               const float* __restrict__ pre_bias,
                               const float* __restrict__ post_bias) {
    constexpr int K = 128;
    constexpr int TILE_M = 64;
    constexpr int LDW = N_OUT + 8;       // halves
    constexpr int LDX = K + 8;           // halves
    constexpr int LDY = N_OUT + 4;       // floats
    constexpr int NF = (N_OUT / 2) / 16; // acc frags per warp (4 or 2)

    extern __shared__ char smem_raw[];
    __half* Ws = (__half*)smem_raw;                       // K x LDW
    __half* Xs = (__half*)(smem_raw + K * LDW * 2);       // TILE_M x LDX
    float*  Ys = (float*)smem_raw;                        // TILE_M x LDY (reused)

    int tid = threadIdx.x;
    int row0 = blockIdx.x * TILE_M;
    int rows = min(TILE_M, n_rows - row0);

    // --- load W (K x N_OUT fp32 row-major) -> fp16 smem ---
    const float4* W4 = (const float4*)W;
    for (int i = tid; i < K * (N_OUT / 4); i += 256) {
        int k = i / (N_OUT / 4);
        int c = (i % (N_OUT / 4)) * 4;
        float4 v = W4[i];
        __half2 p0 = __floats2half2_rn(v.x, v.y);
        __half2 p1 = __floats2half2_rn(v.z, v.w);
        uint2 st; st.x = *(unsigned int*)&p0; st.y = *(unsigned int*)&p1;
        *(uint2*)(Ws + k * LDW + c) = st;
    }

    // --- zero pad rows of Xs (last block) ---
    if (rows < TILE_M) {
        int n_half = (TILE_M - rows) * LDX;
        __half* base = Xs + rows * LDX;
        for (int i = tid; i < n_half; i += 256) base[i] = __ushort_as_half(0);
    }

    // --- load X tile with fused pre-op -> fp16 smem ---
    const float4* X4 = (const float4*)(X + (size_t)row0 * K);
    for (int i = tid; i < rows * (K / 4); i += 256) {
        float4 v = X4[i];
        int r = i / (K / 4);
        int c = (i % (K / 4)) * 4;
        float sa = rs_a[row0 + r];
        if (PRE == 1) {
            v.x *= sa; v.y *= sa; v.z *= sa; v.w *= sa;
        } else {
            v.x = v.x * sa + pre_bias[c + 0];
            v.y = v.y * sa + pre_bias[c + 1];
            v.z = v.z * sa + pre_bias[c + 2];
            v.w = v.w * sa + pre_bias[c + 3];
            if (PRE == 2) {
                float sb = rs_b[row0 + r];
                v.x = fmaxf(v.x, 0.f) * sb;
                v.y = fmaxf(v.y, 0.f) * sb;
                v.z = fmaxf(v.z, 0.f) * sb;
                v.w = fmaxf(v.w, 0.f) * sb;
            }
        }
        __half2 p0 = __floats2half2_rn(v.x, v.y);
        __half2 p1 = __floats2half2_rn(v.z, v.w);
        uint2 st; st.x = *(unsigned int*)&p0; st.y = *(unsigned int*)&p1;
        *(uint2*)(Xs + r * LDX + c) = st;
    }
    __syncthreads();

    // --- compute: 8 warps, warp tile = 16 x (N_OUT/2) ---
    int warp = tid >> 5;
    int warp_m = warp >> 1;              // 0..3
    int warp_n = warp & 1;               // 0..1

    wmma::fragment<wmma::accumulator, 16, 16, 16, float> acc[NF];
    #pragma unroll
    for (int j = 0; j < NF; j++) wmma::fill_fragment(acc[j], 0.0f);

    wmma::fragment<wmma::matrix_a, 16, 16, 16, __half, wmma::row_major> a_frag;
    wmma::fragment<wmma::matrix_b, 16, 16, 16, __half, wmma::row_major> b_frag;

    #pragma unroll
    for (int k = 0; k < K / 16; k++) {
        wmma::load_matrix_sync(a_frag, Xs + (warp_m * 16) * LDX + k * 16, LDX);
        #pragma unroll
        for (int j = 0; j < NF; j++) {
            wmma::load_matrix_sync(b_frag, Ws + (k * 16) * LDW + warp_n * (N_OUT / 2) + j * 16, LDW);
            wmma::mma_sync(acc[j], a_frag, b_frag, acc[j]);
        }
    }
    __syncthreads();   // all smem reads done before Ys overwrites Ws/Xs

    #pragma unroll
    for (int j = 0; j < NF; j++) {
        wmma::store_matrix_sync(Ys + (warp_m * 16) * LDY + warp_n * (N_OUT / 2) + j * 16,
                                acc[j], LDY, wmma::mem_row_major);
    }
    __syncthreads();

    // --- epilogue: bias + convert + store ---
    for (int i = tid; i < rows * (N_OUT / 4); i += 256) {
        int r = i / (N_OUT / 4);
        int c = (i % (N_OUT / 4)) * 4;
        float4 o = *(float4*)(Ys + r * LDY + c);
        if (post_bias) {
            o.x += post_bias[c + 0];
            o.y += post_bias[c + 1];
            o.z += post_bias[c + 2];
            o.w += post_bias[c + 3];
        }
        if (HALF_OUT) {
            __half* Yh = (__half*)Yv;
            __half2 p0 = __floats2half2_rn(o.x, o.y);
            __half2 p1 = __floats2half2_rn(o.z, o.w);
            uint2 st; st.x = *(unsigned int*)&p0; st.y = *(unsigned int*)&p1;
            *(uint2*)(Yh + (size_t)(row0 + r) * N_OUT + c) = st;
        } else {
            *(float4*)((float*)Yv + (size_t)(row0 + r) * N_OUT + c) = o;
        }
    }
}

// ---------------- CSR gather-aggregate (warp per node, 50K independent warps) ----------------
__device__ __forceinline__ void acc_h(float4& a, uint2 v) {
    __half2 h0 = *(__half2*)&v.x;
    __half2 h1 = *(__half2*)&v.y;
    float2 f0 = __half22float2(h0);
    float2 f1 = __half22float2(h1);
    a.x += f0.x; a.y += f0.y; a.z += f1.x; a.w += f1.y;
}

__global__ void gather_kernel(const __half* __restrict__ feat, float* __restrict__ out,
                              const int* __restrict__ offsets, const int* __restrict__ deg,
                              const int* __restrict__ csr_src, int n) {
    int warp = (blockIdx.x * blockDim.x + threadIdx.x) >> 5;
    if (warp >= n) return;
    int lane = threadIdx.x & 31;
    int beg = __ldg(offsets + warp);
    int end = beg + __ldg(deg + warp);

    const uint2* base = (const uint2*)feat;

    float4 a0 = make_float4(0.f, 0.f, 0.f, 0.f);
    float4 a1 = make_float4(0.f, 0.f, 0.f, 0.f);
    float4 a2 = make_float4(0.f, 0.f, 0.f, 0.f);
    float4 a3 = make_float4(0.f, 0.f, 0.f, 0.f);

    int k = beg;
    for (; k + 4 <= end; k += 4) {
        int s0 = __ldg(csr_src + k + 0);
        int s1 = __ldg(csr_src + k + 1);
        int s2 = __ldg(csr_src + k + 2);
        int s3 = __ldg(csr_src + k + 3);
        uint2 v0 = __ldg(base + (size_t)s0 * 32 + lane);
        uint2 v1 = __ldg(base + (size_t)s1 * 32 + lane);
        uint2 v2 = __ldg(base + (size_t)s2 * 32 + lane);
        uint2 v3 = __ldg(base + (size_t)s3 * 32 + lane);
        acc_h(a0, v0);
        acc_h(a1, v1);
        acc_h(a2, v2);
        acc_h(a3, v3);
    }
    for (; k < end; k++) {
        int s = __ldg(csr_src + k);
        uint2 v = __ldg(base + (size_t)s * 32 + lane);
        acc_h(a0, v);
    }
    a0.x += a1.x + a2.x + a3.x;
    a0.y += a1.y + a2.y + a3.y;
    a0.z += a1.z + a2.z + a3.z;
    a0.w += a1.w + a2.w + a3.w;

    *(float4*)(out + (size_t)warp * FEAT + lane * 4) = a0;
}

// ---------------- launch ----------------
extern "C" void kernel_launch(void* const* d_in, const int* in_sizes, int n_in,
                              void* d_out, int out_size) {
    const float* in_feat = (const float*)d_in[0];
    const int*   src     = (const int*)d_in[1];
    const int*   dst     = (const int*)d_in[2];
    const float* W1      = (const float*)d_in[3];
    const float* b1      = (const float*)d_in[4];
    const float* W2      = (const float*)d_in[5];
    const float* b2      = (const float*)d_in[6];
    const float* Wf      = (const float*)d_in[7];
    const float* bf      = (const float*)d_in[8];
    float* out = (float*)d_out;

    int n = in_sizes[0] / FEAT;   // 50000
    int e = in_sizes[1];          // 1600000

    float *buf0, *rs_out, *rs_in;
    __half* h16;
    int *dgo, *dgi, *offs, *curs, *csrc, *segc;
    cudaGetSymbolAddress((void**)&buf0, g_buf0);
    cudaGetSymbolAddress((void**)&h16, g_h16);
    cudaGetSymbolAddress((void**)&rs_out, g_rs_out);
    cudaGetSymbolAddress((void**)&rs_in, g_rs_in);
    cudaGetSymbolAddress((void**)&dgo, g_deg_out);
    cudaGetSymbolAddress((void**)&dgi, g_deg_in);
    cudaGetSymbolAddress((void**)&offs, g_offsets);
    cudaGetSymbolAddress((void**)&curs, g_cursor);
    cudaGetSymbolAddress((void**)&csrc, g_csr_src);
    cudaGetSymbolAddress((void**)&segc, g_seg_counter);

    const int SMEM_128 = 128 * 136 * 2 + 64 * 136 * 2;   // 52224
    const int SMEM_64  = 128 * 72 * 2 + 64 * 136 * 2;    // 35840
    cudaFuncSetAttribute(gemm_tc_kernel<128, 1, 1>, cudaFuncAttributeMaxDynamicSharedMemorySize, SMEM_128);
    cudaFuncSetAttribute(gemm_tc_kernel<128, 2, 1>, cudaFuncAttributeMaxDynamicSharedMemorySize, SMEM_128);
    cudaFuncSetAttribute(gemm_tc_kernel<64, 3, 0>,  cudaFuncAttributeMaxDynamicSharedMemorySize, SMEM_64);

    // degrees + CSR build (graph identical for both layers; build once)
    cudaMemsetAsync(dgo, 0, n * sizeof(int));
    cudaMemsetAsync(dgi, 0, n * sizeof(int));
    cudaMemsetAsync(segc, 0, sizeof(int));

    int e4 = e >> 2;
    count_deg_kernel<<<(e4 + 255) / 256, 256>>>(src, dst, dgo, dgi, e);
    segment_assign_kernel<<<(n + 255) / 256, 256>>>(dgi, dgo, offs, curs, rs_out, rs_in, segc, n);
    csr_fill_kernel<<<(e4 + 255) / 256, 256>>>(src, dst, curs, csrc, e);

    int gemm_blocks = (n + 63) / 64;
    int gather_blocks = (n * 32 + 255) / 256;

    // layer 1: h16 = (x * rs_out) @ W1
    gemm_tc_kernel<128, 1, 1><<<gemm_blocks, 256, SMEM_128>>>(in_feat, W1, h16, n, rs_out, nullptr, nullptr, nullptr);
    gather_kernel<<<gather_blocks, 256>>>(h16, buf0, offs, dgi, csrc, n);

    // layer 2: h16 = (relu(buf0 * rs_in + b1) * rs_out) @ W2
    gemm_tc_kernel<128, 2, 1><<<gemm_blocks, 256, SMEM_128>>>(buf0, W2, h16, n, rs_in, rs_out, b1, nullptr);
    gather_kernel<<<gather_blocks, 256>>>(h16, buf0, offs, dgi, csrc, n);

    // final: out = (buf0 * rs_in + b2) @ Wf + bf
    gemm_tc_kernel<64, 3, 0><<<gemm_blocks, 256, SMEM_64>>>(buf0, Wf, out, n, rs_in, nullptr, b2, bf);
}